// round 1
// baseline (speedup 1.0000x reference)
#include <cuda_runtime.h>

#define BB 4
#define SS 256
#define HH 768
#define N2 1536            // 2*HH
#define MM 1024            // BB*SS
#define NPAIR 32896        // SS*(SS+1)/2

// Scratch for the GEMM result: [MM][N2], first HH cols = g (+bias), last HH = v.
__device__ float g_gv[MM * N2];

// ---------------------------------------------------------------------------
// GEMM: C[m,n] = sum_k X[m,k] * W[(n mod H), (n>=H ? H:0) + k]   (+bias if n<H)
// X: (1024, 768) row-major.  W: (768, 1536) row-major, contraction over W cols.
// Tiles: BM=64, BN=64, BK=16, 256 threads, 4x4 accumulators per thread.
// ---------------------------------------------------------------------------
__global__ __launch_bounds__(256) void gemm_kernel(
    const float* __restrict__ X, const float* __restrict__ W,
    const float* __restrict__ bias)
{
    constexpr int BM = 64, BN = 64, BK = 16;
    __shared__ float As[BK][BM];
    __shared__ float Bs[BK][BN];

    const int t  = threadIdx.x;
    const int bm = blockIdx.y * BM;
    const int bn = blockIdx.x * BN;

    // A tile load mapping: one float4 along k per thread
    const int rowA = t >> 2;            // 0..63
    const int kA   = (t & 3) << 2;      // 0,4,8,12
    // B tile load mapping: one float4 along k per thread (W is k-contiguous per out-col)
    const int colB = t >> 2;            // 0..63  (output column within tile)
    const int kB   = (t & 3) << 2;      // 0,4,8,12

    const int side  = (bn >= HH) ? 1 : 0;       // 0 = g half, 1 = v half
    const int wrow0 = bn - side * HH;           // W row for colB=0
    const int koff  = side * HH;                // k offset into W row

    const int tx = t & 15, ty = t >> 4;

    float acc[4][4] = {};

    const float* Aptr = X + (size_t)(bm + rowA) * HH + kA;
    const float* Wptr = W + (size_t)(wrow0 + colB) * N2 + koff + kB;

    for (int k0 = 0; k0 < HH; k0 += BK) {
        float4 a4 = *(const float4*)(Aptr + k0);
        As[kA + 0][rowA] = a4.x;
        As[kA + 1][rowA] = a4.y;
        As[kA + 2][rowA] = a4.z;
        As[kA + 3][rowA] = a4.w;

        float4 b4 = *(const float4*)(Wptr + k0);
        Bs[kB + 0][colB] = b4.x;
        Bs[kB + 1][colB] = b4.y;
        Bs[kB + 2][colB] = b4.z;
        Bs[kB + 3][colB] = b4.w;

        __syncthreads();

#pragma unroll
        for (int kk = 0; kk < BK; kk++) {
            float4 av = *(const float4*)(&As[kk][ty << 2]);
            float4 bv = *(const float4*)(&Bs[kk][tx << 2]);
            float a_[4] = {av.x, av.y, av.z, av.w};
            float b_[4] = {bv.x, bv.y, bv.z, bv.w};
#pragma unroll
            for (int i = 0; i < 4; i++)
#pragma unroll
                for (int j = 0; j < 4; j++)
                    acc[i][j] = fmaf(a_[i], b_[j], acc[i][j]);
        }
        __syncthreads();
    }

    // Epilogue: add bias to the g half only (g + v + b == (g+b) + v)
    float4 bias4 = make_float4(0.f, 0.f, 0.f, 0.f);
    if (!side) bias4 = *(const float4*)(bias + bn + (tx << 2));

#pragma unroll
    for (int i = 0; i < 4; i++) {
        float4 o;
        o.x = acc[i][0] + bias4.x;
        o.y = acc[i][1] + bias4.y;
        o.z = acc[i][2] + bias4.z;
        o.w = acc[i][3] + bias4.w;
        *(float4*)(g_gv + (size_t)(bm + (ty << 2) + i) * N2 + bn + (tx << 2)) = o;
    }
}

// ---------------------------------------------------------------------------
// Expansion: out[b, p(i,j), :] = tanh(g[b,i,:] + v[b,j,:])   for j >= i
// 8x8 pair tile per CTA, g/v rows staged in smem (48 KB), float4 I/O.
// ---------------------------------------------------------------------------
__global__ __launch_bounds__(256) void expand_kernel(float* __restrict__ out)
{
    constexpr int TI = 8, TJ = 8;
    constexpr int V4 = HH / 4;   // 192 float4 per row
    __shared__ float gs[TI * HH];
    __shared__ float vs[TJ * HH];

    const int b  = blockIdx.z;
    const int i0 = blockIdx.y * TI;
    const int j0 = blockIdx.x * TJ;
    if (j0 + TJ - 1 < i0) return;   // tile fully below the diagonal

    const int t = threadIdx.x;

    // Stage TI g-rows and TJ v-rows (bias already folded into g)
#pragma unroll
    for (int e = t; e < TI * V4; e += 256) {
        int r = e / V4;
        int c = e - r * V4;
        ((float4*)gs)[e] = ((const float4*)(g_gv + (size_t)(b * SS + i0 + r) * N2))[c];
        ((float4*)vs)[e] = ((const float4*)(g_gv + (size_t)(b * SS + j0 + r) * N2 + HH))[c];
    }
    __syncthreads();

    for (int e = t; e < TI * TJ * V4; e += 256) {
        int pair = e / V4;
        int vv   = e - pair * V4;
        int li   = pair >> 3;
        int lj   = pair & 7;
        int i    = i0 + li;
        int j    = j0 + lj;
        if (j < i) continue;

        int p = i * SS - ((i * (i - 1)) >> 1) + (j - i);

        float4 gq = ((const float4*)(gs + li * HH))[vv];
        float4 vq = ((const float4*)(vs + lj * HH))[vv];
        float4 o;
        o.x = tanhf(gq.x + vq.x);
        o.y = tanhf(gq.y + vq.y);
        o.z = tanhf(gq.z + vq.z);
        o.w = tanhf(gq.w + vq.w);

        ((float4*)(out + ((size_t)b * NPAIR + p) * HH))[vv] = o;
    }
}

extern "C" void kernel_launch(void* const* d_in, const int* in_sizes, int n_in,
                              void* d_out, int out_size)
{
    const float* x    = (const float*)d_in[0];  // (4, 256, 768)
    const float* W    = (const float*)d_in[1];  // (768, 1536)
    const float* bias = (const float*)d_in[2];  // (768,)
    float* out = (float*)d_out;                 // (4, 32896, 768)

    dim3 gg(N2 / 64, MM / 64);          // (24, 16)
    gemm_kernel<<<gg, 256>>>(x, W, bias);

    dim3 ge(SS / 8, SS / 8, BB);        // (32, 32, 4)
    expand_kernel<<<ge, 256>>>(out);
}

// round 3
// speedup vs baseline: 1.8009x; 1.8009x over previous
#include <cuda_runtime.h>
#include <cuda_bf16.h>
#include <cstdint>

#define BB 4
#define SS 256
#define HH 768
#define N2 1536
#define MM 1024
#define NPAIR 32896

// GEMM tiling
#define BM 128
#define BN 128
#define BK 32
#define RS 40                 // smem row stride in bf16 elems (80B, bank-conflict-free)
#define PLANE (128 * RS)      // one operand plane (elems)
#define NCHUNK (HH / BK)      // 24

__device__ float g_gv[MM * N2];   // [m][0:768)=g(+bias), [768:1536)=v

// ---------------------------------------------------------------------------
// helpers
// ---------------------------------------------------------------------------
__device__ __forceinline__ void mma16816(float* c, const uint32_t* a, const uint32_t* b) {
    asm volatile(
        "mma.sync.aligned.m16n8k16.row.col.f32.bf16.bf16.f32 "
        "{%0,%1,%2,%3}, {%4,%5,%6,%7}, {%8,%9}, {%0,%1,%2,%3};"
        : "+f"(c[0]), "+f"(c[1]), "+f"(c[2]), "+f"(c[3])
        : "r"(a[0]), "r"(a[1]), "r"(a[2]), "r"(a[3]), "r"(b[0]), "r"(b[1]));
}

// split float4 into packed bf16 hi (leading bits) and lo (residual)
__device__ __forceinline__ void split4(float4 v, uint2& hi, uint2& lo) {
    uint32_t h0, h1;
    asm("cvt.rn.bf16x2.f32 %0, %1, %2;" : "=r"(h0) : "f"(v.y), "f"(v.x));
    asm("cvt.rn.bf16x2.f32 %0, %1, %2;" : "=r"(h1) : "f"(v.w), "f"(v.z));
    float hx = __uint_as_float(h0 << 16);
    float hy = __uint_as_float(h0 & 0xffff0000u);
    float hz = __uint_as_float(h1 << 16);
    float hw = __uint_as_float(h1 & 0xffff0000u);
    uint32_t l0, l1;
    asm("cvt.rn.bf16x2.f32 %0, %1, %2;" : "=r"(l0) : "f"(v.y - hy), "f"(v.x - hx));
    asm("cvt.rn.bf16x2.f32 %0, %1, %2;" : "=r"(l1) : "f"(v.w - hw), "f"(v.z - hz));
    hi = make_uint2(h0, h1);
    lo = make_uint2(l0, l1);
}

// tanh(x) = 1 - 2/(exp(2x)+1), via ~2^-22-accurate MUFU ex2/rcp
__device__ __forceinline__ float fast_tanh(float x) {
    float e;
    asm("ex2.approx.f32 %0, %1;" : "=f"(e) : "f"(x * 2.8853900817779268f));
    float r;
    asm("rcp.approx.f32 %0, %1;" : "=f"(r) : "f"(e + 1.0f));
    return fmaf(-2.0f, r, 1.0f);
}

// ---------------------------------------------------------------------------
// GEMM: g_gv[m][n] = sum_k X[m][k] * B[n][k], B[n][k] = W[n%768][ (n>=768)*768 + k ]
// bf16 hi/lo 3-product compensation, fp32 accumulate via mma.sync (HMMA).
// ---------------------------------------------------------------------------
__global__ __launch_bounds__(256) void mma_gemm(
    const float* __restrict__ X, const float* __restrict__ W,
    const float* __restrict__ bias)
{
    extern __shared__ uint16_t sm[];   // [2 bufs][4 planes: Ahi,Alo,Bhi,Blo][PLANE]

    const int tid  = threadIdx.x;
    const int lane = tid & 31, wid = tid >> 5;
    const int n0 = blockIdx.x * BN;
    const int m0 = blockIdx.y * BM;
    const int side = (n0 >= HH) ? 1 : 0;
    const int wn0  = n0 - side * HH;
    const int koff = side * HH;

    const int mwB = (wid >> 2) * 64;       // warp m offset
    const int nwB = (wid & 3) * 32;        // warp n offset
    const int gr  = lane >> 2;             // 0..7
    const int gc  = (lane & 3) << 1;       // 0,2,4,6

    // gmem<->smem slots: 4 float4 per thread per operand
    const float* aP[4];
    const float* bP[4];
    int soff[4];
#pragma unroll
    for (int q = 0; q < 4; q++) {
        int f = q * 256 + tid;
        int r = f >> 3, c = f & 7;
        aP[q] = X + (size_t)(m0 + r) * HH + c * 4;
        bP[q] = W + (size_t)(wn0 + r) * N2 + koff + c * 4;
        soff[q] = r * RS + c * 4;
    }

    float acc[4][4][4] = {};
    float4 pa[4], pb[4];

    // prologue: chunk 0 -> buf 0
#pragma unroll
    for (int q = 0; q < 4; q++) { pa[q] = *(const float4*)aP[q]; pb[q] = *(const float4*)bP[q]; }
#pragma unroll
    for (int q = 0; q < 4; q++) {
        uint2 hi, lo;
        split4(pa[q], hi, lo);
        *(uint2*)(sm + 0 * PLANE + soff[q]) = hi;
        *(uint2*)(sm + 1 * PLANE + soff[q]) = lo;
        split4(pb[q], hi, lo);
        *(uint2*)(sm + 2 * PLANE + soff[q]) = hi;
        *(uint2*)(sm + 3 * PLANE + soff[q]) = lo;
    }
    __syncthreads();

#pragma unroll 1
    for (int ch = 0; ch < NCHUNK; ch++) {
        const int buf = ch & 1;

        // prefetch next chunk into registers
        if (ch < NCHUNK - 1) {
            const int k0 = (ch + 1) * BK;
#pragma unroll
            for (int q = 0; q < 4; q++) {
                pa[q] = *(const float4*)(aP[q] + k0);
                pb[q] = *(const float4*)(bP[q] + k0);
            }
        }

        // compute on buf
        const uint16_t* Ah = sm + (buf * 4 + 0) * PLANE;
        const uint16_t* Al = sm + (buf * 4 + 1) * PLANE;
        const uint16_t* Bh = sm + (buf * 4 + 2) * PLANE;
        const uint16_t* Bl = sm + (buf * 4 + 3) * PLANE;

#pragma unroll
        for (int ks = 0; ks < 2; ks++) {
            const int kc = ks * 16 + gc;
            uint32_t ahi[4][4], alo[4][4], bhi[4][2], blo[4][2];
#pragma unroll
            for (int mt = 0; mt < 4; mt++) {
                const int r = mwB + mt * 16 + gr;
                const uint16_t* p = Ah + r * RS + kc;
                ahi[mt][0] = *(const uint32_t*)p;
                ahi[mt][1] = *(const uint32_t*)(p + 8 * RS);
                ahi[mt][2] = *(const uint32_t*)(p + 8);
                ahi[mt][3] = *(const uint32_t*)(p + 8 * RS + 8);
                const uint16_t* q_ = Al + r * RS + kc;
                alo[mt][0] = *(const uint32_t*)q_;
                alo[mt][1] = *(const uint32_t*)(q_ + 8 * RS);
                alo[mt][2] = *(const uint32_t*)(q_ + 8);
                alo[mt][3] = *(const uint32_t*)(q_ + 8 * RS + 8);
            }
#pragma unroll
            for (int nt = 0; nt < 4; nt++) {
                const int n = nwB + nt * 8 + gr;
                const uint16_t* p = Bh + n * RS + kc;
                bhi[nt][0] = *(const uint32_t*)p;
                bhi[nt][1] = *(const uint32_t*)(p + 8);
                const uint16_t* q_ = Bl + n * RS + kc;
                blo[nt][0] = *(const uint32_t*)q_;
                blo[nt][1] = *(const uint32_t*)(q_ + 8);
            }
#pragma unroll
            for (int mt = 0; mt < 4; mt++)
#pragma unroll
                for (int nt = 0; nt < 4; nt++)
                    mma16816(acc[mt][nt], ahi[mt], bhi[nt]);
#pragma unroll
            for (int mt = 0; mt < 4; mt++)
#pragma unroll
                for (int nt = 0; nt < 4; nt++)
                    mma16816(acc[mt][nt], ahi[mt], blo[nt]);
#pragma unroll
            for (int mt = 0; mt < 4; mt++)
#pragma unroll
                for (int nt = 0; nt < 4; nt++)
                    mma16816(acc[mt][nt], alo[mt], bhi[nt]);
        }
        __syncthreads();

        // store prefetched chunk into the other buffer
        if (ch < NCHUNK - 1) {
            const int ob = buf ^ 1;
#pragma unroll
            for (int q = 0; q < 4; q++) {
                uint2 hi, lo;
                split4(pa[q], hi, lo);
                *(uint2*)(sm + (ob * 4 + 0) * PLANE + soff[q]) = hi;
                *(uint2*)(sm + (ob * 4 + 1) * PLANE + soff[q]) = lo;
                split4(pb[q], hi, lo);
                *(uint2*)(sm + (ob * 4 + 2) * PLANE + soff[q]) = hi;
                *(uint2*)(sm + (ob * 4 + 3) * PLANE + soff[q]) = lo;
            }
            __syncthreads();
        }
    }

    // epilogue: fp32 out + bias on g half
#pragma unroll
    for (int mt = 0; mt < 4; mt++) {
#pragma unroll
        for (int nt = 0; nt < 4; nt++) {
            const int r = m0 + mwB + mt * 16 + gr;
            const int c = n0 + nwB + nt * 8 + gc;
            float b0 = 0.f, b1 = 0.f;
            if (!side) { b0 = bias[c]; b1 = bias[c + 1]; }
            float* p = g_gv + (size_t)r * N2 + c;
            float2 v0, v1;
            v0.x = acc[mt][nt][0] + b0;
            v0.y = acc[mt][nt][1] + b1;
            v1.x = acc[mt][nt][2] + b0;
            v1.y = acc[mt][nt][3] + b1;
            *(float2*)p = v0;
            *(float2*)(p + 8 * N2) = v1;
        }
    }
}

// ---------------------------------------------------------------------------
// Expansion: out[b, p(i,j), :] = tanh(g[b,i,:] + v[b,j,:])  (j >= i)
// ---------------------------------------------------------------------------
__global__ __launch_bounds__(256) void expand_kernel(float* __restrict__ out)
{
    constexpr int V4 = HH / 4;  // 192
    __shared__ float gs[8 * HH];
    __shared__ float vs[8 * HH];

    const int b  = blockIdx.z;
    const int i0 = blockIdx.y * 8;
    const int j0 = blockIdx.x * 8;
    if (j0 + 7 < i0) return;

    const int t = threadIdx.x;
#pragma unroll
    for (int e = t; e < 8 * V4; e += 256) {
        int r = e / V4, c = e - r * V4;
        ((float4*)gs)[e] = ((const float4*)(g_gv + (size_t)(b * SS + i0 + r) * N2))[c];
        ((float4*)vs)[e] = ((const float4*)(g_gv + (size_t)(b * SS + j0 + r) * N2 + HH))[c];
    }
    __syncthreads();

    const int wid = t >> 5, lid = t & 31;
    const int i = i0 + wid;
    const float4* gp = (const float4*)(gs + wid * HH);
    const int pbase = i * SS - ((i * (i - 1)) >> 1) - i;  // p = pbase + j

    for (int lj = 0; lj < 8; ++lj) {
        const int j = j0 + lj;
        if (j < i) continue;
        const float4* vp = (const float4*)(vs + lj * HH);
        float4* op = (float4*)(out + ((size_t)b * NPAIR + pbase + j) * HH);
#pragma unroll
        for (int q = 0; q < 6; q++) {
            const int vv = lid + q * 32;
            float4 g4 = gp[vv], v4 = vp[vv];
            float4 o;
            o.x = fast_tanh(g4.x + v4.x);
            o.y = fast_tanh(g4.y + v4.y);
            o.z = fast_tanh(g4.z + v4.z);
            o.w = fast_tanh(g4.w + v4.w);
            __stcs(op + vv, o);
        }
    }
}

extern "C" void kernel_launch(void* const* d_in, const int* in_sizes, int n_in,
                              void* d_out, int out_size)
{
    const float* x    = (const float*)d_in[0];
    const float* W    = (const float*)d_in[1];
    const float* bias = (const float*)d_in[2];
    float* out = (float*)d_out;

    static int smem_set = 0;
    if (!smem_set) {
        cudaFuncSetAttribute(mma_gemm, cudaFuncAttributeMaxDynamicSharedMemorySize,
                             2 * 4 * PLANE * (int)sizeof(uint16_t));
        smem_set = 1;
    }

    mma_gemm<<<dim3(N2 / BN, MM / BM), 256, 2 * 4 * PLANE * sizeof(uint16_t)>>>(x, W, bias);
    expand_kernel<<<dim3(SS / 8, SS / 8, BB), 256>>>(out);
}

// round 4
// speedup vs baseline: 1.8728x; 1.0399x over previous
#include <cuda_runtime.h>
#include <cuda_bf16.h>
#include <cstdint>

#define BB 4
#define SS 256
#define HH 768
#define N2 1536
#define MM 1024
#define NPAIR 32896

// GEMM tiling
#define BM 64
#define BN 128
#define BK 32
#define RS 40                   // smem row stride in bf16 elems (80B, conflict-free)
#define APLANE (BM * RS)        // 2560 elems
#define BPLANE (BN * RS)        // 5120 elems
#define BUFSZ (2 * APLANE + 2 * BPLANE)   // 15360 elems per buffer
#define NCHUNK (HH / BK)        // 24

__device__ float g_gv[MM * N2];   // [m][0:768)=g(+bias), [768:1536)=v

// ---------------------------------------------------------------------------
// helpers
// ---------------------------------------------------------------------------
__device__ __forceinline__ void mma16816(float* c, const uint32_t* a, const uint32_t* b) {
    asm volatile(
        "mma.sync.aligned.m16n8k16.row.col.f32.bf16.bf16.f32 "
        "{%0,%1,%2,%3}, {%4,%5,%6,%7}, {%8,%9}, {%0,%1,%2,%3};"
        : "+f"(c[0]), "+f"(c[1]), "+f"(c[2]), "+f"(c[3])
        : "r"(a[0]), "r"(a[1]), "r"(a[2]), "r"(a[3]), "r"(b[0]), "r"(b[1]));
}

// split float4 into packed bf16 hi (leading bits) and lo (residual)
__device__ __forceinline__ void split4(float4 v, uint2& hi, uint2& lo) {
    uint32_t h0, h1;
    asm("cvt.rn.bf16x2.f32 %0, %1, %2;" : "=r"(h0) : "f"(v.y), "f"(v.x));
    asm("cvt.rn.bf16x2.f32 %0, %1, %2;" : "=r"(h1) : "f"(v.w), "f"(v.z));
    float hx = __uint_as_float(h0 << 16);
    float hy = __uint_as_float(h0 & 0xffff0000u);
    float hz = __uint_as_float(h1 << 16);
    float hw = __uint_as_float(h1 & 0xffff0000u);
    uint32_t l0, l1;
    asm("cvt.rn.bf16x2.f32 %0, %1, %2;" : "=r"(l0) : "f"(v.y - hy), "f"(v.x - hx));
    asm("cvt.rn.bf16x2.f32 %0, %1, %2;" : "=r"(l1) : "f"(v.w - hw), "f"(v.z - hz));
    hi = make_uint2(h0, h1);
    lo = make_uint2(l0, l1);
}

__device__ __forceinline__ float fast_tanh(float x) {
    float y;
    asm("tanh.approx.f32 %0, %1;" : "=f"(y) : "f"(x));
    return y;
}

// ---------------------------------------------------------------------------
// GEMM: g_gv[m][n] = sum_k X[m][k] * B[n][k], B[n][k] = W[n%768][ (n>=768)*768 + k ]
// bf16 hi/lo 3-product compensation, fp32 accumulate via mma.sync (HMMA).
// BM=64, BN=128 -> 192 CTAs; warp tile 32x32 (2 warp-rows x 4 warp-cols).
// ---------------------------------------------------------------------------
__global__ __launch_bounds__(256, 2) void mma_gemm(
    const float* __restrict__ X, const float* __restrict__ W,
    const float* __restrict__ bias)
{
    extern __shared__ uint16_t sm[];   // [2 bufs][Ahi|Alo|Bhi|Blo]

    const int tid  = threadIdx.x;
    const int lane = tid & 31, wid = tid >> 5;
    const int n0 = blockIdx.x * BN;
    const int m0 = blockIdx.y * BM;
    const int side = (n0 >= HH) ? 1 : 0;
    const int wn0  = n0 - side * HH;
    const int koff = side * HH;

    const int mwB = (wid >> 2) * 32;       // warp m offset (0/32)
    const int nwB = (wid & 3) * 32;        // warp n offset (0..96)
    const int gr  = lane >> 2;             // 0..7
    const int gc  = (lane & 3) << 1;       // 0,2,4,6

    // gmem<->smem slots: 2 A float4 + 4 B float4 per thread
    const float* aP[2];
    const float* bP[4];
    int aOff[2], bOff[4];
#pragma unroll
    for (int q = 0; q < 2; q++) {
        int f = q * 256 + tid;
        int r = f >> 3, c = f & 7;
        aP[q] = X + (size_t)(m0 + r) * HH + c * 4;
        aOff[q] = r * RS + c * 4;
    }
#pragma unroll
    for (int q = 0; q < 4; q++) {
        int f = q * 256 + tid;
        int r = f >> 3, c = f & 7;
        bP[q] = W + (size_t)(wn0 + r) * N2 + koff + c * 4;
        bOff[q] = r * RS + c * 4;
    }

    float acc[2][4][4] = {};
    float4 pa[2], pb[4];

    // prologue: chunk 0 -> buf 0
#pragma unroll
    for (int q = 0; q < 2; q++) pa[q] = *(const float4*)aP[q];
#pragma unroll
    for (int q = 0; q < 4; q++) pb[q] = *(const float4*)bP[q];
#pragma unroll
    for (int q = 0; q < 2; q++) {
        uint2 hi, lo;
        split4(pa[q], hi, lo);
        *(uint2*)(sm + 0 * APLANE + aOff[q]) = hi;
        *(uint2*)(sm + 1 * APLANE + aOff[q]) = lo;
    }
#pragma unroll
    for (int q = 0; q < 4; q++) {
        uint2 hi, lo;
        split4(pb[q], hi, lo);
        *(uint2*)(sm + 2 * APLANE + bOff[q]) = hi;
        *(uint2*)(sm + 2 * APLANE + BPLANE + bOff[q]) = lo;
    }
    __syncthreads();

#pragma unroll 1
    for (int ch = 0; ch < NCHUNK; ch++) {
        const int buf = ch & 1;

        // prefetch next chunk into registers
        if (ch < NCHUNK - 1) {
            const int k0 = (ch + 1) * BK;
#pragma unroll
            for (int q = 0; q < 2; q++) pa[q] = *(const float4*)(aP[q] + k0);
#pragma unroll
            for (int q = 0; q < 4; q++) pb[q] = *(const float4*)(bP[q] + k0);
        }

        const uint16_t* Ah = sm + buf * BUFSZ;
        const uint16_t* Al = Ah + APLANE;
        const uint16_t* Bh = Al + APLANE;
        const uint16_t* Bl = Bh + BPLANE;

#pragma unroll
        for (int ks = 0; ks < 2; ks++) {
            const int kc = ks * 16 + gc;
            uint32_t ahi[2][4], alo[2][4], bhi[4][2], blo[4][2];
#pragma unroll
            for (int mt = 0; mt < 2; mt++) {
                const int r = mwB + mt * 16 + gr;
                const uint16_t* p = Ah + r * RS + kc;
                ahi[mt][0] = *(const uint32_t*)p;
                ahi[mt][1] = *(const uint32_t*)(p + 8 * RS);
                ahi[mt][2] = *(const uint32_t*)(p + 8);
                ahi[mt][3] = *(const uint32_t*)(p + 8 * RS + 8);
                const uint16_t* q_ = Al + r * RS + kc;
                alo[mt][0] = *(const uint32_t*)q_;
                alo[mt][1] = *(const uint32_t*)(q_ + 8 * RS);
                alo[mt][2] = *(const uint32_t*)(q_ + 8);
                alo[mt][3] = *(const uint32_t*)(q_ + 8 * RS + 8);
            }
#pragma unroll
            for (int nt = 0; nt < 4; nt++) {
                const int n = nwB + nt * 8 + gr;
                const uint16_t* p = Bh + n * RS + kc;
                bhi[nt][0] = *(const uint32_t*)p;
                bhi[nt][1] = *(const uint32_t*)(p + 8);
                const uint16_t* q_ = Bl + n * RS + kc;
                blo[nt][0] = *(const uint32_t*)q_;
                blo[nt][1] = *(const uint32_t*)(q_ + 8);
            }
#pragma unroll
            for (int mt = 0; mt < 2; mt++)
#pragma unroll
                for (int nt = 0; nt < 4; nt++)
                    mma16816(acc[mt][nt], ahi[mt], bhi[nt]);
#pragma unroll
            for (int mt = 0; mt < 2; mt++)
#pragma unroll
                for (int nt = 0; nt < 4; nt++)
                    mma16816(acc[mt][nt], ahi[mt], blo[nt]);
#pragma unroll
            for (int mt = 0; mt < 2; mt++)
#pragma unroll
                for (int nt = 0; nt < 4; nt++)
                    mma16816(acc[mt][nt], alo[mt], bhi[nt]);
        }
        __syncthreads();

        // store prefetched chunk into the other buffer
        if (ch < NCHUNK - 1) {
            const int ob = buf ^ 1;
            uint16_t* D = sm + ob * BUFSZ;
#pragma unroll
            for (int q = 0; q < 2; q++) {
                uint2 hi, lo;
                split4(pa[q], hi, lo);
                *(uint2*)(D + 0 * APLANE + aOff[q]) = hi;
                *(uint2*)(D + 1 * APLANE + aOff[q]) = lo;
            }
#pragma unroll
            for (int q = 0; q < 4; q++) {
                uint2 hi, lo;
                split4(pb[q], hi, lo);
                *(uint2*)(D + 2 * APLANE + bOff[q]) = hi;
                *(uint2*)(D + 2 * APLANE + BPLANE + bOff[q]) = lo;
            }
            __syncthreads();
        }
    }

    // epilogue: fp32 out + bias on g half
#pragma unroll
    for (int mt = 0; mt < 2; mt++) {
#pragma unroll
        for (int nt = 0; nt < 4; nt++) {
            const int r = m0 + mwB + mt * 16 + gr;
            const int c = n0 + nwB + nt * 8 + gc;
            float b0 = 0.f, b1 = 0.f;
            if (!side) { b0 = bias[c]; b1 = bias[c + 1]; }
            float* p = g_gv + (size_t)r * N2 + c;
            float2 v0, v1;
            v0.x = acc[mt][nt][0] + b0;
            v0.y = acc[mt][nt][1] + b1;
            v1.x = acc[mt][nt][2] + b0;
            v1.y = acc[mt][nt][3] + b1;
            *(float2*)p = v0;
            *(float2*)(p + 8 * N2) = v1;
        }
    }
}

// ---------------------------------------------------------------------------
// Expansion: out[b, p(i,j), :] = tanh(g[b,i,:] + v[b,j,:])  (j >= i)
// ---------------------------------------------------------------------------
__global__ __launch_bounds__(256) void expand_kernel(float* __restrict__ out)
{
    constexpr int V4 = HH / 4;  // 192
    __shared__ float gs[8 * HH];
    __shared__ float vs[8 * HH];

    const int b  = blockIdx.z;
    const int i0 = blockIdx.y * 8;
    const int j0 = blockIdx.x * 8;
    if (j0 + 7 < i0) return;

    const int t = threadIdx.x;
#pragma unroll
    for (int e = t; e < 8 * V4; e += 256) {
        int r = e / V4, c = e - r * V4;
        ((float4*)gs)[e] = ((const float4*)(g_gv + (size_t)(b * SS + i0 + r) * N2))[c];
        ((float4*)vs)[e] = ((const float4*)(g_gv + (size_t)(b * SS + j0 + r) * N2 + HH))[c];
    }
    __syncthreads();

    const int wid = t >> 5, lid = t & 31;
    const int i = i0 + wid;
    const float4* gp = (const float4*)(gs + wid * HH);
    const int pbase = i * SS - ((i * (i - 1)) >> 1) - i;  // p = pbase + j

    for (int lj = 0; lj < 8; ++lj) {
        const int j = j0 + lj;
        if (j < i) continue;
        const float4* vp = (const float4*)(vs + lj * HH);
        float4* op = (float4*)(out + ((size_t)b * NPAIR + pbase + j) * HH);
#pragma unroll
        for (int q = 0; q < 6; q++) {
            const int vv = lid + q * 32;
            float4 g4 = gp[vv], v4 = vp[vv];
            float4 o;
            o.x = fast_tanh(g4.x + v4.x);
            o.y = fast_tanh(g4.y + v4.y);
            o.z = fast_tanh(g4.z + v4.z);
            o.w = fast_tanh(g4.w + v4.w);
            __stcs(op + vv, o);
        }
    }
}

extern "C" void kernel_launch(void* const* d_in, const int* in_sizes, int n_in,
                              void* d_out, int out_size)
{
    const float* x    = (const float*)d_in[0];
    const float* W    = (const float*)d_in[1];
    const float* bias = (const float*)d_in[2];
    float* out = (float*)d_out;

    static int smem_set = 0;
    if (!smem_set) {
        cudaFuncSetAttribute(mma_gemm, cudaFuncAttributeMaxDynamicSharedMemorySize,
                             2 * BUFSZ * (int)sizeof(uint16_t));
        smem_set = 1;
    }

    mma_gemm<<<dim3(N2 / BN, MM / BM), 256, 2 * BUFSZ * sizeof(uint16_t)>>>(x, W, bias);
    expand_kernel<<<dim3(SS / 8, SS / 8, BB), 256>>>(out);
}

// round 5
// speedup vs baseline: 1.9176x; 1.0239x over previous
#include <cuda_runtime.h>
#include <cuda_bf16.h>
#include <cstdint>

#define BB 4
#define SS 256
#define HH 768
#define N2 1536
#define MM 1024
#define NPAIR 32896

// GEMM tiling
#define BM 64
#define BN 128
#define BK 32
#define RS 40                   // smem row stride in bf16 elems (80B, conflict-free)
#define APLANE (BM * RS)        // 2560 elems
#define BPLANE (BN * RS)        // 5120 elems
#define BUFSZ (2 * APLANE + 2 * BPLANE)   // 15360 elems per buffer
#define NCHUNK (HH / BK)        // 24

__device__ float g_gv[MM * N2];   // [m][0:768)=g(+bias), [768:1536)=v

// ---------------------------------------------------------------------------
// helpers
// ---------------------------------------------------------------------------
__device__ __forceinline__ uint32_t smem_u32(const void* p) {
    uint32_t a;
    asm("{ .reg .u64 t; cvta.to.shared.u64 t, %1; cvt.u32.u64 %0, t; }" : "=r"(a) : "l"(p));
    return a;
}

__device__ __forceinline__ void ldsm_x4(uint32_t* r, uint32_t addr) {
    asm volatile("ldmatrix.sync.aligned.m8n8.x4.shared.b16 {%0,%1,%2,%3}, [%4];"
                 : "=r"(r[0]), "=r"(r[1]), "=r"(r[2]), "=r"(r[3]) : "r"(addr));
}

__device__ __forceinline__ void mma16816(float* c, const uint32_t* a, const uint32_t* b) {
    asm volatile(
        "mma.sync.aligned.m16n8k16.row.col.f32.bf16.bf16.f32 "
        "{%0,%1,%2,%3}, {%4,%5,%6,%7}, {%8,%9}, {%0,%1,%2,%3};"
        : "+f"(c[0]), "+f"(c[1]), "+f"(c[2]), "+f"(c[3])
        : "r"(a[0]), "r"(a[1]), "r"(a[2]), "r"(a[3]), "r"(b[0]), "r"(b[1]));
}

// split float4 into packed bf16 hi (leading bits) and lo (residual)
__device__ __forceinline__ void split4(float4 v, uint2& hi, uint2& lo) {
    uint32_t h0, h1;
    asm("cvt.rn.bf16x2.f32 %0, %1, %2;" : "=r"(h0) : "f"(v.y), "f"(v.x));
    asm("cvt.rn.bf16x2.f32 %0, %1, %2;" : "=r"(h1) : "f"(v.w), "f"(v.z));
    float hx = __uint_as_float(h0 << 16);
    float hy = __uint_as_float(h0 & 0xffff0000u);
    float hz = __uint_as_float(h1 << 16);
    float hw = __uint_as_float(h1 & 0xffff0000u);
    uint32_t l0, l1;
    asm("cvt.rn.bf16x2.f32 %0, %1, %2;" : "=r"(l0) : "f"(v.y - hy), "f"(v.x - hx));
    asm("cvt.rn.bf16x2.f32 %0, %1, %2;" : "=r"(l1) : "f"(v.w - hw), "f"(v.z - hz));
    hi = make_uint2(h0, h1);
    lo = make_uint2(l0, l1);
}

__device__ __forceinline__ float fast_tanh(float x) {
    float y;
    asm("tanh.approx.f32 %0, %1;" : "=f"(y) : "f"(x));
    return y;
}

// ---------------------------------------------------------------------------
// GEMM: g_gv[m][n] = sum_k X[m][k] * B[n][k], B[n][k] = W[n%768][ (n>=768)*768 + k ]
// bf16 hi/lo 3-product compensation, fp32 accumulate, ldmatrix fragment loads.
// ---------------------------------------------------------------------------
__global__ __launch_bounds__(256, 2) void mma_gemm(
    const float* __restrict__ X, const float* __restrict__ W,
    const float* __restrict__ bias)
{
    extern __shared__ uint16_t sm[];   // [2 bufs][Ahi|Alo|Bhi|Blo]
    const uint32_t sbase = smem_u32(sm);

    const int tid  = threadIdx.x;
    const int lane = tid & 31, wid = tid >> 5;
    const int n0 = blockIdx.x * BN;
    const int m0 = blockIdx.y * BM;
    const int side = (n0 >= HH) ? 1 : 0;
    const int wn0  = n0 - side * HH;
    const int koff = side * HH;

    const int mwB = (wid >> 2) * 32;       // warp m offset (0/32)
    const int nwB = (wid & 3) * 32;        // warp n offset (0..96)
    const int gr  = lane >> 2;             // 0..7
    const int gc  = (lane & 3) << 1;       // 0,2,4,6

    // ldmatrix lane addressing terms (elements)
    const int lrow = lane & 7;
    const int q    = lane >> 3;
    int aTerm[2], bTerm[2];
#pragma unroll
    for (int mt = 0; mt < 2; mt++)
        aTerm[mt] = (mwB + mt * 16 + (q & 1) * 8 + lrow) * RS + (q >> 1) * 8;
#pragma unroll
    for (int u = 0; u < 2; u++)
        bTerm[u] = (nwB + u * 16 + (q >> 1) * 8 + lrow) * RS + (q & 1) * 8;

    // gmem<->smem slots: 2 A float4 + 4 B float4 per thread
    const float* aP[2];
    const float* bP[4];
    int aOff[2], bOff[4];
#pragma unroll
    for (int qq = 0; qq < 2; qq++) {
        int f = qq * 256 + tid;
        int r = f >> 3, c = f & 7;
        aP[qq] = X + (size_t)(m0 + r) * HH + c * 4;
        aOff[qq] = r * RS + c * 4;
    }
#pragma unroll
    for (int qq = 0; qq < 4; qq++) {
        int f = qq * 256 + tid;
        int r = f >> 3, c = f & 7;
        bP[qq] = W + (size_t)(wn0 + r) * N2 + koff + c * 4;
        bOff[qq] = r * RS + c * 4;
    }

    float acc[2][4][4] = {};
    float4 pa[2], pb[4];

    // prefetch chunk 0
#pragma unroll
    for (int qq = 0; qq < 2; qq++) pa[qq] = *(const float4*)aP[qq];
#pragma unroll
    for (int qq = 0; qq < 4; qq++) pb[qq] = *(const float4*)bP[qq];

#pragma unroll 1
    for (int ch = 0; ch < NCHUNK; ch++) {
        const int buf = ch & 1;
        uint16_t* D = sm + buf * BUFSZ;

        // store prefetched chunk into current buffer
#pragma unroll
        for (int qq = 0; qq < 2; qq++) {
            uint2 hi, lo;
            split4(pa[qq], hi, lo);
            *(uint2*)(D + 0 * APLANE + aOff[qq]) = hi;
            *(uint2*)(D + 1 * APLANE + aOff[qq]) = lo;
        }
#pragma unroll
        for (int qq = 0; qq < 4; qq++) {
            uint2 hi, lo;
            split4(pb[qq], hi, lo);
            *(uint2*)(D + 2 * APLANE + bOff[qq]) = hi;
            *(uint2*)(D + 2 * APLANE + BPLANE + bOff[qq]) = lo;
        }
        __syncthreads();

        // prefetch next chunk (overlaps with compute below)
        if (ch < NCHUNK - 1) {
            const int k0 = (ch + 1) * BK;
#pragma unroll
            for (int qq = 0; qq < 2; qq++) pa[qq] = *(const float4*)(aP[qq] + k0);
#pragma unroll
            for (int qq = 0; qq < 4; qq++) pb[qq] = *(const float4*)(bP[qq] + k0);
        }

        // compute on current buffer (ldmatrix fragment loads)
        const uint32_t Ah = sbase + (uint32_t)(buf * BUFSZ) * 2;
        const uint32_t Al = Ah + APLANE * 2;
        const uint32_t Bh = Al + APLANE * 2;
        const uint32_t Bl = Bh + BPLANE * 2;

#pragma unroll
        for (int ks = 0; ks < 2; ks++) {
            const uint32_t kb = (uint32_t)(ks * 16) * 2;
            uint32_t ahi[2][4], alo[2][4], bhi[4][2], blo[4][2];
#pragma unroll
            for (int mt = 0; mt < 2; mt++) {
                ldsm_x4(ahi[mt], Ah + (uint32_t)aTerm[mt] * 2 + kb);
                ldsm_x4(alo[mt], Al + (uint32_t)aTerm[mt] * 2 + kb);
            }
#pragma unroll
            for (int u = 0; u < 2; u++) {
                uint32_t rh[4], rl[4];
                ldsm_x4(rh, Bh + (uint32_t)bTerm[u] * 2 + kb);
                ldsm_x4(rl, Bl + (uint32_t)bTerm[u] * 2 + kb);
                bhi[2 * u][0] = rh[0]; bhi[2 * u][1] = rh[1];
                bhi[2 * u + 1][0] = rh[2]; bhi[2 * u + 1][1] = rh[3];
                blo[2 * u][0] = rl[0]; blo[2 * u][1] = rl[1];
                blo[2 * u + 1][0] = rl[2]; blo[2 * u + 1][1] = rl[3];
            }
#pragma unroll
            for (int mt = 0; mt < 2; mt++)
#pragma unroll
                for (int nt = 0; nt < 4; nt++)
                    mma16816(acc[mt][nt], ahi[mt], bhi[nt]);
#pragma unroll
            for (int mt = 0; mt < 2; mt++)
#pragma unroll
                for (int nt = 0; nt < 4; nt++)
                    mma16816(acc[mt][nt], ahi[mt], blo[nt]);
#pragma unroll
            for (int mt = 0; mt < 2; mt++)
#pragma unroll
                for (int nt = 0; nt < 4; nt++)
                    mma16816(acc[mt][nt], alo[mt], bhi[nt]);
        }
    }

    // epilogue: fp32 out + bias on g half
#pragma unroll
    for (int mt = 0; mt < 2; mt++) {
#pragma unroll
        for (int nt = 0; nt < 4; nt++) {
            const int r = m0 + mwB + mt * 16 + gr;
            const int c = n0 + nwB + nt * 8 + gc;
            float b0 = 0.f, b1 = 0.f;
            if (!side) { b0 = bias[c]; b1 = bias[c + 1]; }
            float* p = g_gv + (size_t)r * N2 + c;
            float2 v0, v1;
            v0.x = acc[mt][nt][0] + b0;
            v0.y = acc[mt][nt][1] + b1;
            v1.x = acc[mt][nt][2] + b0;
            v1.y = acc[mt][nt][3] + b1;
            *(float2*)p = v0;
            *(float2*)(p + 8 * N2) = v1;
        }
    }
}

// ---------------------------------------------------------------------------
// Expansion: out[b, p(i,j), :] = tanh(g[b,i,:] + v[b,j,:])  (j >= i)
// Warp owns row i (g kept in 24 registers); v rows staged in 24KB smem.
// ---------------------------------------------------------------------------
__global__ __launch_bounds__(256, 4) void expand_kernel(float* __restrict__ out)
{
    constexpr int V4 = HH / 4;  // 192
    __shared__ float vs[8 * HH];

    const int b  = blockIdx.z;
    const int i0 = blockIdx.y * 8;
    const int j0 = blockIdx.x * 8;
    if (j0 + 7 < i0) return;

    const int t = threadIdx.x;
    const int wid = t >> 5, lid = t & 31;

    // stage 8 v rows
#pragma unroll
    for (int e = t; e < 8 * V4; e += 256) {
        int r = e / V4, c = e - r * V4;
        ((float4*)vs)[e] = ((const float4*)(g_gv + (size_t)(b * SS + j0 + r) * N2 + HH))[c];
    }

    // g row for this warp -> registers (bias already folded in)
    const int i = i0 + wid;
    const float4* gsrc = (const float4*)(g_gv + (size_t)(b * SS + i) * N2);
    float4 gr4[6];
#pragma unroll
    for (int qq = 0; qq < 6; qq++) gr4[qq] = gsrc[lid + qq * 32];

    __syncthreads();

    const int pbase = i * SS - ((i * (i - 1)) >> 1) - i;  // p = pbase + j

    for (int lj = 0; lj < 8; ++lj) {
        const int j = j0 + lj;
        if (j < i) continue;
        const float4* vp = (const float4*)(vs + lj * HH);
        float4* op = (float4*)(out + ((size_t)b * NPAIR + pbase + j) * HH);
#pragma unroll
        for (int qq = 0; qq < 6; qq++) {
            const int vv = lid + qq * 32;
            float4 v4 = vp[vv];
            float4 o;
            o.x = fast_tanh(gr4[qq].x + v4.x);
            o.y = fast_tanh(gr4[qq].y + v4.y);
            o.z = fast_tanh(gr4[qq].z + v4.z);
            o.w = fast_tanh(gr4[qq].w + v4.w);
            __stcs(op + vv, o);
        }
    }
}

extern "C" void kernel_launch(void* const* d_in, const int* in_sizes, int n_in,
                              void* d_out, int out_size)
{
    const float* x    = (const float*)d_in[0];
    const float* W    = (const float*)d_in[1];
    const float* bias = (const float*)d_in[2];
    float* out = (float*)d_out;

    static int smem_set = 0;
    if (!smem_set) {
        cudaFuncSetAttribute(mma_gemm, cudaFuncAttributeMaxDynamicSharedMemorySize,
                             2 * BUFSZ * (int)sizeof(uint16_t));
        smem_set = 1;
    }

    mma_gemm<<<dim3(N2 / BN, MM / BM), 256, 2 * BUFSZ * sizeof(uint16_t)>>>(x, W, bias);
    expand_kernel<<<dim3(SS / 8, SS / 8, BB), 256>>>(out);
}